// round 7
// baseline (speedup 1.0000x reference)
#include <cuda_runtime.h>
#include <cuda_bf16.h>

#define N_NODES 100000
#define N_EDGES 625000
#define GRID1_BLOCKS 444   // 3 blocks/SM * 148 SMs, persistent grid-stride

// Combined per-node projection table: g_AB[n] = {a0+bias0, a1+bias1, b0, b1}
__device__ float4 g_AB[N_NODES];

// ---- packed f32x2 helpers (ptxas won't auto-fuse; PTX-only) ----
__device__ __forceinline__ unsigned long long pack2(float lo, float hi) {
    unsigned long long r;
    asm("mov.b64 %0, {%1, %2};" : "=l"(r) : "f"(lo), "f"(hi));
    return r;
}
__device__ __forceinline__ void unpack2(unsigned long long p, float& lo, float& hi) {
    asm("mov.b64 {%0, %1}, %2;" : "=f"(lo), "=f"(hi) : "l"(p));
}
__device__ __forceinline__ unsigned long long fma2(unsigned long long a,
                                                   unsigned long long b,
                                                   unsigned long long c) {
    unsigned long long d;
    asm("fma.rn.f32x2 %0, %1, %2, %3;" : "=l"(d) : "l"(a), "l"(b), "l"(c));
    return d;
}
// dot-accumulate: acc += v*w (elementwise over 4 floats, packed as 2x f32x2)
__device__ __forceinline__ unsigned long long dot4_acc(float4 v, float4 w,
                                                       unsigned long long acc) {
    acc = fma2(pack2(v.x, v.y), pack2(w.x, w.y), acc);
    acc = fma2(pack2(v.z, v.w), pack2(w.z, w.w), acc);
    return acc;
}
__device__ __forceinline__ float hsum2(unsigned long long p) {
    float lo, hi; unpack2(p, lo, hi); return lo + hi;
}

// Persistent: 8 lanes per node-pair group, 4 groups per warp, 2 nodes per group.
// Warp-granular grid-stride over 12500 groups of 8 nodes (exact, no tail).
__global__ __launch_bounds__(256, 3) void node_proj_kernel(
    const float4* __restrict__ x,    // [N_NODES * 32] float4
    const float4* __restrict__ W,    // [2 * 64] float4
    const float*  __restrict__ bias) // [2]
{
    int lane = threadIdx.x & 31;
    int g = lane >> 3;        // group 0..3
    int w = lane & 7;         // lane-in-group 0..7
    int warp_global = blockIdx.x * 8 + (threadIdx.x >> 5);
    const int n_warps = GRID1_BLOCKS * 8;
    const int N_GROUPS = N_NODES / 8;   // 12500 exactly

    float bi0 = __ldg(&bias[0]);
    float bi1 = __ldg(&bias[1]);

    for (int grp = warp_global; grp < N_GROUPS; grp += n_warps) {
        int nodeA = grp * 8 + g;
        int nodeB = nodeA + 4;

        // Front-batched streaming loads (evict-first: x has zero reuse).
        const float4* xa = x + nodeA * 32;
        const float4* xb = x + nodeB * 32;
        float4 u0 = __ldcs(&xa[w]);
        float4 u1 = __ldcs(&xa[w + 8]);
        float4 u2 = __ldcs(&xa[w + 16]);
        float4 u3 = __ldcs(&xa[w + 24]);
        float4 v0 = __ldcs(&xb[w]);
        float4 v1 = __ldcs(&xb[w + 8]);
        float4 v2 = __ldcs(&xb[w + 16]);
        float4 v3 = __ldcs(&xb[w + 24]);

        unsigned long long ua0 = 0, ua1 = 0, ub0 = 0, ub1 = 0;  // node A
        unsigned long long va0 = 0, va1 = 0, vb0 = 0, vb1 = 0;  // node B

        #pragma unroll
        for (int j = 0; j < 4; j++) {
            float4 u = (j == 0) ? u0 : (j == 1) ? u1 : (j == 2) ? u2 : u3;
            float4 v = (j == 0) ? v0 : (j == 1) ? v1 : (j == 2) ? v2 : v3;
            int col = w + 8 * j;
            float4 wa0 = __ldg(&W[col]);        // class0 src half
            float4 wb0 = __ldg(&W[32 + col]);   // class0 dst half
            float4 wa1 = __ldg(&W[64 + col]);   // class1 src half
            float4 wb1 = __ldg(&W[96 + col]);   // class1 dst half

            ua0 = dot4_acc(u, wa0, ua0);
            ub0 = dot4_acc(u, wb0, ub0);
            ua1 = dot4_acc(u, wa1, ua1);
            ub1 = dot4_acc(u, wb1, ub1);
            va0 = dot4_acc(v, wa0, va0);
            vb0 = dot4_acc(v, wb0, vb0);
            va1 = dot4_acc(v, wa1, va1);
            vb1 = dot4_acc(v, wb1, vb1);
        }

        float sa0 = hsum2(ua0), sa1 = hsum2(ua1), sb0 = hsum2(ub0), sb1 = hsum2(ub1);
        float ta0 = hsum2(va0), ta1 = hsum2(va1), tb0 = hsum2(vb0), tb1 = hsum2(vb1);

        #pragma unroll
        for (int off = 4; off > 0; off >>= 1) {
            sa0 += __shfl_down_sync(0xFFFFFFFFu, sa0, off);
            sa1 += __shfl_down_sync(0xFFFFFFFFu, sa1, off);
            sb0 += __shfl_down_sync(0xFFFFFFFFu, sb0, off);
            sb1 += __shfl_down_sync(0xFFFFFFFFu, sb1, off);
            ta0 += __shfl_down_sync(0xFFFFFFFFu, ta0, off);
            ta1 += __shfl_down_sync(0xFFFFFFFFu, ta1, off);
            tb0 += __shfl_down_sync(0xFFFFFFFFu, tb0, off);
            tb1 += __shfl_down_sync(0xFFFFFFFFu, tb1, off);
        }

        if (w == 0) {
            g_AB[nodeA] = make_float4(sa0 + bi0, sa1 + bi1, sb0, sb1);
            g_AB[nodeB] = make_float4(ta0 + bi0, ta1 + bi1, tb0, tb1);
        }
    }

#if __CUDA_ARCH__ >= 900
    cudaTriggerProgrammaticLaunchCompletion();
#endif
}

// 2 edges per thread. PDL: load indices (independent of g_AB) before the
// grid-dependency-sync. Streaming hints keep the g_AB table L2-resident.
__global__ __launch_bounds__(256) void edge_score_kernel(
    const int2* __restrict__ src2,   // ei[0:E] as int2
    const int2* __restrict__ dst2,   // ei[E:2E] as int2
    float4* __restrict__ out4)       // 2 edges per float4
{
    int t = blockIdx.x * blockDim.x + threadIdx.x;

    int2 s = make_int2(0, 0), d = make_int2(0, 0);
    bool valid = (t < N_EDGES / 2);
    if (valid) {
        s = __ldcs(&src2[t]);
        d = __ldcs(&dst2[t]);
    }

#if __CUDA_ARCH__ >= 900
    cudaGridDependencySynchronize();
#endif

    if (!valid) return;

    const float2* AB = (const float2*)g_AB;  // A at 2*n, B at 2*n+1
    float2 A0 = AB[2 * s.x],     A1 = AB[2 * s.y];
    float2 B0 = AB[2 * d.x + 1], B1 = AB[2 * d.y + 1];

    __stcs(&out4[t], make_float4(A0.x + B0.x, A0.y + B0.y,
                                 A1.x + B1.x, A1.y + B1.y));
}

extern "C" void kernel_launch(void* const* d_in, const int* in_sizes, int n_in,
                              void* d_out, int out_size)
{
    const float4* x    = (const float4*)d_in[0];   // [100000, 128] f32
    const int*    ei   = (const int*)d_in[1];      // [2, 625000] i32
    const float4* W    = (const float4*)d_in[2];   // [2, 256] f32
    const float*  b    = (const float*)d_in[3];    // [2] f32
    const int2*   src2 = (const int2*)ei;
    const int2*   dst2 = (const int2*)(ei + N_EDGES);
    float4*       out4 = (float4*)d_out;

    // Kernel 1: persistent grid (3 blocks/SM), grid-stride over node groups.
    node_proj_kernel<<<GRID1_BLOCKS, 256>>>(x, W, b);

    // Kernel 2: per-edge gather with programmatic dependent launch.
    int grid2 = (N_EDGES / 2 + 255) / 256;

    cudaLaunchConfig_t cfg = {};
    cfg.gridDim  = dim3((unsigned)grid2, 1, 1);
    cfg.blockDim = dim3(256, 1, 1);
    cfg.dynamicSmemBytes = 0;
    cfg.stream = 0;
    cudaLaunchAttribute attrs[1];
    attrs[0].id = cudaLaunchAttributeProgrammaticStreamSerialization;
    attrs[0].val.programmaticStreamSerializationAllowed = 1;
    cfg.attrs = attrs;
    cfg.numAttrs = 1;

    cudaError_t err = cudaLaunchKernelEx(&cfg, edge_score_kernel, src2, dst2, out4);
    if (err != cudaSuccess) {
        edge_score_kernel<<<grid2, 256>>>(src2, dst2, out4);
    }
}

// round 8
// speedup vs baseline: 1.4290x; 1.4290x over previous
#include <cuda_runtime.h>
#include <cuda_bf16.h>

#define N_NODES 100000
#define N_EDGES 625000
#define GRID1_BLOCKS 592   // persistent grid; grid-stride self-balances

// Combined per-node projection table: g_AB[n] = {a0+bias0, a1+bias1, b0, b1}
__device__ float4 g_AB[N_NODES];

// 8 lanes per node-pair group, 4 groups per warp, 2 nodes per group -> 8 nodes/warp.
// Persistent warp-granular grid-stride over 12500 groups (exact division, no tail).
__global__ __launch_bounds__(256) void node_proj_kernel(
    const float4* __restrict__ x,    // [N_NODES * 32] float4
    const float4* __restrict__ W,    // [2 * 64] float4
    const float*  __restrict__ bias) // [2]
{
    int lane = threadIdx.x & 31;
    int g = lane >> 3;        // group 0..3
    int w = lane & 7;         // lane-in-group 0..7
    int warp_global = blockIdx.x * 8 + (threadIdx.x >> 5);
    const int n_warps = GRID1_BLOCKS * 8;
    const int N_GROUPS = N_NODES / 8;   // 12500 exactly

    float bi0 = __ldg(&bias[0]);
    float bi1 = __ldg(&bias[1]);

    for (int grp = warp_global; grp < N_GROUPS; grp += n_warps) {
        int nodeA = grp * 8 + g;
        int nodeB = nodeA + 4;

        const float4* xa = x + nodeA * 32;
        const float4* xb = x + nodeB * 32;
        float4 u0 = xa[w];
        float4 u1 = xa[w + 8];
        float4 u2 = xa[w + 16];
        float4 u3 = xa[w + 24];
        float4 v0 = xb[w];
        float4 v1 = xb[w + 8];
        float4 v2 = xb[w + 16];
        float4 v3 = xb[w + 24];

        float ua0 = 0.f, ua1 = 0.f, ub0 = 0.f, ub1 = 0.f;   // node A
        float va0 = 0.f, va1 = 0.f, vb0 = 0.f, vb1 = 0.f;   // node B

        #pragma unroll
        for (int j = 0; j < 4; j++) {
            float4 u = (j == 0) ? u0 : (j == 1) ? u1 : (j == 2) ? u2 : u3;
            float4 v = (j == 0) ? v0 : (j == 1) ? v1 : (j == 2) ? v2 : v3;
            int col = w + 8 * j;
            float4 wa0 = __ldg(&W[col]);        // class0 src half
            float4 wb0 = __ldg(&W[32 + col]);   // class0 dst half
            float4 wa1 = __ldg(&W[64 + col]);   // class1 src half
            float4 wb1 = __ldg(&W[96 + col]);   // class1 dst half

            ua0 += u.x * wa0.x + u.y * wa0.y + u.z * wa0.z + u.w * wa0.w;
            ub0 += u.x * wb0.x + u.y * wb0.y + u.z * wb0.z + u.w * wb0.w;
            ua1 += u.x * wa1.x + u.y * wa1.y + u.z * wa1.z + u.w * wa1.w;
            ub1 += u.x * wb1.x + u.y * wb1.y + u.z * wb1.z + u.w * wb1.w;

            va0 += v.x * wa0.x + v.y * wa0.y + v.z * wa0.z + v.w * wa0.w;
            vb0 += v.x * wb0.x + v.y * wb0.y + v.z * wb0.z + v.w * wb0.w;
            va1 += v.x * wa1.x + v.y * wa1.y + v.z * wa1.z + v.w * wa1.w;
            vb1 += v.x * wb1.x + v.y * wb1.y + v.z * wb1.z + v.w * wb1.w;
        }

        #pragma unroll
        for (int off = 4; off > 0; off >>= 1) {
            ua0 += __shfl_down_sync(0xFFFFFFFFu, ua0, off);
            ua1 += __shfl_down_sync(0xFFFFFFFFu, ua1, off);
            ub0 += __shfl_down_sync(0xFFFFFFFFu, ub0, off);
            ub1 += __shfl_down_sync(0xFFFFFFFFu, ub1, off);
            va0 += __shfl_down_sync(0xFFFFFFFFu, va0, off);
            va1 += __shfl_down_sync(0xFFFFFFFFu, va1, off);
            vb0 += __shfl_down_sync(0xFFFFFFFFu, vb0, off);
            vb1 += __shfl_down_sync(0xFFFFFFFFu, vb1, off);
        }

        if (w == 0) {
            g_AB[nodeA] = make_float4(ua0 + bi0, ua1 + bi1, ub0, ub1);
            g_AB[nodeB] = make_float4(va0 + bi0, va1 + bi1, vb0, vb1);
        }
    }

#if __CUDA_ARCH__ >= 900
    cudaTriggerProgrammaticLaunchCompletion();
#endif
}

// 2 edges per thread. PDL: load indices (independent of g_AB) before the
// grid-dependency-sync. Bias folded into A.
__global__ __launch_bounds__(256) void edge_score_kernel(
    const int2* __restrict__ src2,   // ei[0:E] as int2
    const int2* __restrict__ dst2,   // ei[E:2E] as int2
    float4* __restrict__ out4)       // 2 edges per float4
{
    int t = blockIdx.x * blockDim.x + threadIdx.x;

    int2 s = make_int2(0, 0), d = make_int2(0, 0);
    bool valid = (t < N_EDGES / 2);
    if (valid) {
        s = __ldg(&src2[t]);
        d = __ldg(&dst2[t]);
    }

#if __CUDA_ARCH__ >= 900
    cudaGridDependencySynchronize();
#endif

    if (!valid) return;

    const float2* AB = (const float2*)g_AB;  // A at 2*n, B at 2*n+1
    float2 A0 = AB[2 * s.x],     A1 = AB[2 * s.y];
    float2 B0 = AB[2 * d.x + 1], B1 = AB[2 * d.y + 1];

    out4[t] = make_float4(A0.x + B0.x, A0.y + B0.y, A1.x + B1.x, A1.y + B1.y);
}

extern "C" void kernel_launch(void* const* d_in, const int* in_sizes, int n_in,
                              void* d_out, int out_size)
{
    const float4* x    = (const float4*)d_in[0];   // [100000, 128] f32
    const int*    ei   = (const int*)d_in[1];      // [2, 625000] i32
    const float4* W    = (const float4*)d_in[2];   // [2, 256] f32
    const float*  b    = (const float*)d_in[3];    // [2] f32
    const int2*   src2 = (const int2*)ei;
    const int2*   dst2 = (const int2*)(ei + N_EDGES);
    float4*       out4 = (float4*)d_out;

    // Kernel 1: persistent grid-stride over node groups.
    node_proj_kernel<<<GRID1_BLOCKS, 256>>>(x, W, b);

    // Kernel 2: per-edge gather with programmatic dependent launch.
    int grid2 = (N_EDGES / 2 + 255) / 256;

    cudaLaunchConfig_t cfg = {};
    cfg.gridDim  = dim3((unsigned)grid2, 1, 1);
    cfg.blockDim = dim3(256, 1, 1);
    cfg.dynamicSmemBytes = 0;
    cfg.stream = 0;
    cudaLaunchAttribute attrs[1];
    attrs[0].id = cudaLaunchAttributeProgrammaticStreamSerialization;
    attrs[0].val.programmaticStreamSerializationAllowed = 1;
    cfg.attrs = attrs;
    cfg.numAttrs = 1;

    cudaError_t err = cudaLaunchKernelEx(&cfg, edge_score_kernel, src2, dst2, out4);
    if (err != cudaSuccess) {
        edge_score_kernel<<<grid2, 256>>>(src2, dst2, out4);
    }
}